// round 6
// baseline (speedup 1.0000x reference)
#include <cuda_runtime.h>
#include <cuda_bf16.h>
#include <cstdint>

// COO SpMM: CSR build (hist -> scan -> scatter), then edge-balanced SpMM.
// out[i,:] = sum_{e: rows[e]==i} vals[e] * embeds[cols[e],:]

#define N_NODES 100000
#define N_EDGES 1600000
#define D_FEAT  48
#define EPG     64            // edges per 16-lane group (fixed work unit)
#define ROW_MASK 0x3fffffff
#define HEAD_BIT (1 << 30)

#define SCAN_N   (N_NODES + 1)          // 100001
#define SCAN_BLK 1024
#define SCAN_NB  ((SCAN_N + SCAN_BLK - 1) / SCAN_BLK)   // 98

// Scratch (static device globals — zero-initialized at module load).
// Invariant: g_counts all-zero at entry (scan re-zeroes after consuming);
// g_desc zeroed by hist block 0 before the scan kernel reads it.
__device__ int  g_counts[SCAN_N];
__device__ int  g_offs[SCAN_N];
__device__ int  g_rank[N_EDGES];                 // edge's rank within its row
__device__ unsigned long long g_desc[SCAN_NB];   // lookback: flag<<62 | sum
__device__ int4 g_edges[N_EDGES];                // {col, val_bits, row|head, 0}

// ---------- pass 1: histogram + ranks + zero lookback state + zero out ----------
__global__ void hist_kernel(const int4* __restrict__ rows4, int n4,
                            float4* __restrict__ out4, int nout4) {
    if (blockIdx.x == 0 && threadIdx.x < SCAN_NB)
        g_desc[threadIdx.x] = 0ULL;
    int i = blockIdx.x * blockDim.x + threadIdx.x;
    int stride = gridDim.x * blockDim.x;
    // zero the output (needed for the SpMM's atomic boundary flushes)
    for (int j = i; j < nout4; j += stride)
        out4[j] = make_float4(0.f, 0.f, 0.f, 0.f);
    if (i < n4) {
        int4 r = __ldg(&rows4[i]);
        int4 k;
        k.x = atomicAdd(&g_counts[r.x], 1);
        k.y = atomicAdd(&g_counts[r.y], 1);
        k.z = atomicAdd(&g_counts[r.z], 1);
        k.w = atomicAdd(&g_counts[r.w], 1);
        ((int4*)g_rank)[i] = k;   // coalesced store of ranks
    }
}

// ---------- pass 2: single-launch exclusive scan (decoupled lookback) ----------
// 98 blocks, all co-resident on 148+ SMs => lookback is deadlock-free.
__global__ void __launch_bounds__(SCAN_BLK)
scan_lookback_kernel() {
    __shared__ int warp_sums[32];
    __shared__ int s_exclusive;

    int bid = blockIdx.x;
    int i = bid * SCAN_BLK + threadIdx.x;
    int v = (i < SCAN_N) ? g_counts[i] : 0;
    if (i < SCAN_N) g_counts[i] = 0;      // restore zero invariant

    int lane = threadIdx.x & 31, wid = threadIdx.x >> 5;

    int inc = v;
#pragma unroll
    for (int d = 1; d < 32; d <<= 1) {
        int t = __shfl_up_sync(0xffffffffu, inc, d);
        if (lane >= d) inc += t;
    }
    if (lane == 31) warp_sums[wid] = inc;
    __syncthreads();
    if (wid == 0) {
        int s = warp_sums[lane];
#pragma unroll
        for (int d = 1; d < 32; d <<= 1) {
            int t = __shfl_up_sync(0xffffffffu, s, d);
            if (lane >= d) s += t;
        }
        warp_sums[lane] = s;
    }
    __syncthreads();
    int base = (wid > 0) ? warp_sums[wid - 1] : 0;
    int local_excl = base + inc - v;
    int block_sum = warp_sums[31];

    if (threadIdx.x == 0) {
        unsigned long long flag = (bid == 0) ? 2ULL : 1ULL;
        *(volatile unsigned long long*)&g_desc[bid] =
            (flag << 62) | (unsigned long long)(unsigned)block_sum;
        __threadfence();
        if (bid == 0) s_exclusive = 0;
    }

    if (bid > 0 && wid == 0) {
        int exclusive = 0;
        int j = bid - 1;
        while (true) {
            int idx = j - lane;
            int flag, val;
            if (idx >= 0) {
                unsigned long long d;
                do {
                    d = *(volatile unsigned long long*)&g_desc[idx];
                    flag = (int)(d >> 62);
                } while (flag == 0);
                val = (int)(d & 0xffffffffULL);
            } else { flag = 2; val = 0; }
            unsigned mask = __ballot_sync(0xffffffffu, flag == 2);
            int contrib;
            if (mask) {
                int steps = __ffs(mask) - 1;
                contrib = (lane <= steps) ? val : 0;
            } else {
                contrib = val;
            }
#pragma unroll
            for (int d = 16; d; d >>= 1)
                contrib += __shfl_down_sync(0xffffffffu, contrib, d);
            contrib = __shfl_sync(0xffffffffu, contrib, 0);
            exclusive += contrib;
            if (mask) break;
            j -= 32;
        }
        if (lane == 0) {
            __threadfence();
            *(volatile unsigned long long*)&g_desc[bid] =
                (2ULL << 62) | (unsigned long long)(unsigned)(exclusive + block_sum);
            s_exclusive = exclusive;
        }
    }
    __syncthreads();

    if (i < SCAN_N) g_offs[i] = s_exclusive + local_excl;
}

// ---------- pass 3: scatter edges (no atomics; row id + head flag embedded) ----------
__global__ void scatter_kernel(const int4* __restrict__ rows4,
                               const int4* __restrict__ cols4,
                               const float4* __restrict__ vals4, int n4) {
    int i = blockIdx.x * blockDim.x + threadIdx.x;
    if (i < n4) {
        int4   r = __ldg(&rows4[i]);
        int4   c = __ldg(&cols4[i]);
        float4 v = __ldg(&vals4[i]);
        int4   k = ((const int4*)g_rank)[i];
        int p0 = __ldg(&g_offs[r.x]) + k.x;
        int p1 = __ldg(&g_offs[r.y]) + k.y;
        int p2 = __ldg(&g_offs[r.z]) + k.z;
        int p3 = __ldg(&g_offs[r.w]) + k.w;
        g_edges[p0] = make_int4(c.x, __float_as_int(v.x), r.x | (k.x == 0 ? HEAD_BIT : 0), 0);
        g_edges[p1] = make_int4(c.y, __float_as_int(v.y), r.y | (k.y == 0 ? HEAD_BIT : 0), 0);
        g_edges[p2] = make_int4(c.z, __float_as_int(v.z), r.z | (k.z == 0 ? HEAD_BIT : 0), 0);
        g_edges[p3] = make_int4(c.w, __float_as_int(v.w), r.w | (k.w == 0 ? HEAD_BIT : 0), 0);
    }
}

// ---------- pass 4: edge-balanced SpMM ----------
// Each 16-lane group owns EPG consecutive edges (fixed work => perfect balance).
// Edges read sequentially (L1-resident after first touch). Rows fully inside
// the chunk are stored directly; split rows are flushed with red.add (out is
// zero-initialized by hist_kernel).
__device__ __forceinline__ void flush_row(float* __restrict__ out, int r, int lane,
                                          float a0, float a1, float a2, bool complete) {
    float* o = out + (size_t)r * D_FEAT + lane;
    if (complete) {
        o[0] = a0; o[16] = a1; o[32] = a2;
    } else {
        asm volatile("red.global.add.f32 [%0], %1;" :: "l"(o)      , "f"(a0) : "memory");
        asm volatile("red.global.add.f32 [%0], %1;" :: "l"(o + 16) , "f"(a1) : "memory");
        asm volatile("red.global.add.f32 [%0], %1;" :: "l"(o + 32) , "f"(a2) : "memory");
    }
}

__global__ void __launch_bounds__(256)
spmm_merge_kernel(const float* __restrict__ embeds, float* __restrict__ out,
                  int n_edges) {
    int group = blockIdx.x * 16 + (threadIdx.x >> 4);
    int lane  = threadIdx.x & 15;
    int c0 = group * EPG;
    if (c0 >= n_edges) return;
    int c1 = min(c0 + EPG, n_edges);    // EPG even, n_edges multiple of 64

    float a0 = 0.f, a1 = 0.f, a2 = 0.f;
    int  r_cur = -1;
    bool head  = false;

    for (int e = c0; e < c1; e += 2) {
        int4 E0 = __ldg(&g_edges[e]);
        int4 E1 = __ldg(&g_edges[e + 1]);
        // issue all gathers up front (6 independent loads in flight)
        const float* b0 = embeds + (size_t)E0.x * D_FEAT + lane;
        const float* b1 = embeds + (size_t)E1.x * D_FEAT + lane;
        float x0 = __ldg(b0), x1 = __ldg(b0 + 16), x2 = __ldg(b0 + 32);
        float y0 = __ldg(b1), y1 = __ldg(b1 + 16), y2 = __ldg(b1 + 32);

        int r0 = E0.z & ROW_MASK;
        if (r0 != r_cur) {
            if (r_cur >= 0) flush_row(out, r_cur, lane, a0, a1, a2, head); // row ended interior
            a0 = a1 = a2 = 0.f;
            r_cur = r0;
            head = (E0.z & HEAD_BIT) != 0;
        }
        float v0 = __int_as_float(E0.y);
        a0 += v0 * x0; a1 += v0 * x1; a2 += v0 * x2;

        int r1 = E1.z & ROW_MASK;
        if (r1 != r_cur) {
            flush_row(out, r_cur, lane, a0, a1, a2, head);
            a0 = a1 = a2 = 0.f;
            r_cur = r1;
            head = (E1.z & HEAD_BIT) != 0;
        }
        float v1 = __int_as_float(E1.y);
        a0 += v1 * y0; a1 += v1 * y1; a2 += v1 * y2;
    }

    // final flush: complete iff row started in-chunk AND ends at chunk boundary
    bool ends = true;
    if (c1 < n_edges) {
        int zn = __ldg(&((const int*)g_edges)[(size_t)c1 * 4 + 2]);
        ends = ((zn & ROW_MASK) != r_cur);
    }
    flush_row(out, r_cur, lane, a0, a1, a2, head && ends);
}

extern "C" void kernel_launch(void* const* d_in, const int* in_sizes, int n_in,
                              void* d_out, int out_size) {
    const int*   rows   = (const int*)d_in[0];
    const int*   cols   = (const int*)d_in[1];
    const float* vals   = (const float*)d_in[2];
    const float* embeds = (const float*)d_in[3];
    float* out = (float*)d_out;

    int n_edges = in_sizes[0];
    int n4 = n_edges / 4;           // 1.6M divisible by 4
    int nout4 = out_size / 4;       // 1.2M float4

    hist_kernel<<<(n4 + 255) / 256, 256>>>((const int4*)rows, n4,
                                           (float4*)out, nout4);
    scan_lookback_kernel<<<SCAN_NB, SCAN_BLK>>>();
    scatter_kernel<<<(n4 + 255) / 256, 256>>>((const int4*)rows, (const int4*)cols,
                                              (const float4*)vals, n4);
    int groups = (n_edges + EPG - 1) / EPG;           // 25000
    spmm_merge_kernel<<<(groups + 15) / 16, 256>>>(embeds, out, n_edges);
}

// round 7
// speedup vs baseline: 1.1268x; 1.1268x over previous
#include <cuda_runtime.h>
#include <cuda_bf16.h>
#include <cstdint>

// COO SpMM via on-the-fly CSR build, then 8-lane-group float2 gather SpMM.
// out[i,:] = sum_{e: rows[e]==i} vals[e] * embeds[cols[e],:]

#define N_NODES 100000
#define N_EDGES 1600000
#define D_FEAT  48
#define D_F2    24           // row = 24 float2

#define SCAN_N   (N_NODES + 1)          // 100001
#define SCAN_BLK 1024
#define SCAN_NB  ((SCAN_N + SCAN_BLK - 1) / SCAN_BLK)   // 98

// Scratch (static device globals — zero-initialized at module load).
// Invariant: g_counts all-zero at entry (scan re-zeroes after consuming);
// g_desc zeroed by hist block 0 before the scan kernel reads it.
__device__ int  g_counts[SCAN_N];
__device__ int  g_offs[SCAN_N];
__device__ int  g_rank[N_EDGES];                 // edge's rank within its row
__device__ unsigned long long g_desc[SCAN_NB];   // lookback: flag<<62 | sum
__device__ int2 g_edges[N_EDGES];                // {col, val_as_int}

// ---------- pass 1: histogram + per-edge rank (int4) + zero lookback state ----------
__global__ void hist_kernel(const int4* __restrict__ rows4, int n4) {
    if (blockIdx.x == 0 && threadIdx.x < SCAN_NB)
        g_desc[threadIdx.x] = 0ULL;
    int i = blockIdx.x * blockDim.x + threadIdx.x;
    if (i < n4) {
        int4 r = __ldg(&rows4[i]);
        int4 k;
        k.x = atomicAdd(&g_counts[r.x], 1);
        k.y = atomicAdd(&g_counts[r.y], 1);
        k.z = atomicAdd(&g_counts[r.z], 1);
        k.w = atomicAdd(&g_counts[r.w], 1);
        ((int4*)g_rank)[i] = k;   // coalesced store of ranks
    }
}

// ---------- pass 2: single-launch exclusive scan (decoupled lookback) ----------
// 98 blocks, all co-resident on 148+ SMs => lookback is deadlock-free.
__global__ void __launch_bounds__(SCAN_BLK)
scan_lookback_kernel() {
    __shared__ int warp_sums[32];
    __shared__ int s_exclusive;

    int bid = blockIdx.x;
    int i = bid * SCAN_BLK + threadIdx.x;
    int v = (i < SCAN_N) ? g_counts[i] : 0;
    if (i < SCAN_N) g_counts[i] = 0;      // restore zero invariant

    int lane = threadIdx.x & 31, wid = threadIdx.x >> 5;

    int inc = v;
#pragma unroll
    for (int d = 1; d < 32; d <<= 1) {
        int t = __shfl_up_sync(0xffffffffu, inc, d);
        if (lane >= d) inc += t;
    }
    if (lane == 31) warp_sums[wid] = inc;
    __syncthreads();
    if (wid == 0) {
        int s = warp_sums[lane];
#pragma unroll
        for (int d = 1; d < 32; d <<= 1) {
            int t = __shfl_up_sync(0xffffffffu, s, d);
            if (lane >= d) s += t;
        }
        warp_sums[lane] = s;
    }
    __syncthreads();
    int base = (wid > 0) ? warp_sums[wid - 1] : 0;
    int local_excl = base + inc - v;
    int block_sum = warp_sums[31];

    if (threadIdx.x == 0) {
        unsigned long long flag = (bid == 0) ? 2ULL : 1ULL;
        *(volatile unsigned long long*)&g_desc[bid] =
            (flag << 62) | (unsigned long long)(unsigned)block_sum;
        __threadfence();
        if (bid == 0) s_exclusive = 0;
    }

    if (bid > 0 && wid == 0) {
        int exclusive = 0;
        int j = bid - 1;
        while (true) {
            int idx = j - lane;
            int flag, val;
            if (idx >= 0) {
                unsigned long long d;
                do {
                    d = *(volatile unsigned long long*)&g_desc[idx];
                    flag = (int)(d >> 62);
                } while (flag == 0);
                val = (int)(d & 0xffffffffULL);
            } else { flag = 2; val = 0; }
            unsigned mask = __ballot_sync(0xffffffffu, flag == 2);
            int contrib;
            if (mask) {
                int steps = __ffs(mask) - 1;
                contrib = (lane <= steps) ? val : 0;
            } else {
                contrib = val;
            }
#pragma unroll
            for (int d = 16; d; d >>= 1)
                contrib += __shfl_down_sync(0xffffffffu, contrib, d);
            contrib = __shfl_sync(0xffffffffu, contrib, 0);
            exclusive += contrib;
            if (mask) break;
            j -= 32;
        }
        if (lane == 0) {
            __threadfence();
            *(volatile unsigned long long*)&g_desc[bid] =
                (2ULL << 62) | (unsigned long long)(unsigned)(exclusive + block_sum);
            s_exclusive = exclusive;
        }
    }
    __syncthreads();

    if (i < SCAN_N) g_offs[i] = s_exclusive + local_excl;
}

// ---------- pass 3: scatter edges into CSR bins (no atomics) ----------
__global__ void scatter_kernel(const int4* __restrict__ rows4,
                               const int4* __restrict__ cols4,
                               const float4* __restrict__ vals4, int n4) {
    int i = blockIdx.x * blockDim.x + threadIdx.x;
    if (i < n4) {
        int4   r = __ldg(&rows4[i]);
        int4   c = __ldg(&cols4[i]);
        float4 v = __ldg(&vals4[i]);
        int4   k = ((const int4*)g_rank)[i];
        int p0 = __ldg(&g_offs[r.x]) + k.x;
        int p1 = __ldg(&g_offs[r.y]) + k.y;
        int p2 = __ldg(&g_offs[r.z]) + k.z;
        int p3 = __ldg(&g_offs[r.w]) + k.w;
        g_edges[p0] = make_int2(c.x, __float_as_int(v.x));
        g_edges[p1] = make_int2(c.y, __float_as_int(v.y));
        g_edges[p2] = make_int2(c.z, __float_as_int(v.z));
        g_edges[p3] = make_int2(c.w, __float_as_int(v.w));
    }
}

// ---------- pass 4: 8-lane-group float2 gather SpMM ----------
// Group of 8 lanes owns one row; lane gl covers float2 feats {gl, gl+8, gl+16}.
// Edges prefetched 8 at a time (coalesced LDG.64 per group), broadcast via
// shfl(width=8). Outer loop is warp-uniform (trip = warp-max row length) so
// all shfl_sync calls are convergent; per-group work is predicated.
// 100000 rows = 3125 blocks x 32 groups exactly (no remainder, no early exit).
__global__ void __launch_bounds__(256)
spmm_csr_kernel(const float2* __restrict__ embeds2,   // [N, 24] float2
                float2* __restrict__ out2) {          // [N, 24] float2
    int row = blockIdx.x * 32 + (threadIdx.x >> 3);
    int gl  = threadIdx.x & 7;

    int s = g_offs[row];
    int t = g_offs[row + 1];
    int len = t - s;

    // warp-wide max trip count (keeps outer loop convergent)
    int wmax = len;
#pragma unroll
    for (int off = 16; off; off >>= 1)
        wmax = max(wmax, __shfl_xor_sync(0xffffffffu, wmax, off));

    float ax0 = 0.f, ay0 = 0.f, ax1 = 0.f, ay1 = 0.f, ax2 = 0.f, ay2 = 0.f;

    for (int j = 0; j < wmax; j += 8) {
        int idx = s + j + gl;
        int2 e = (j + gl < len) ? __ldg(&g_edges[idx]) : make_int2(0, 0);
        int m = len - j;   // uniform within group; may be <=0 for short rows
#pragma unroll
        for (int k = 0; k < 8; k++) {
            int col = __shfl_sync(0xffffffffu, e.x, k, 8);
            int vb  = __shfl_sync(0xffffffffu, e.y, k, 8);
            if (k < m) {
                const float2* b = embeds2 + (size_t)col * D_F2 + gl;
                float2 x0 = __ldg(b);
                float2 x1 = __ldg(b + 8);
                float2 x2 = __ldg(b + 16);
                float v = __int_as_float(vb);
                ax0 += v * x0.x; ay0 += v * x0.y;
                ax1 += v * x1.x; ay1 += v * x1.y;
                ax2 += v * x2.x; ay2 += v * x2.y;
            }
        }
    }

    float2* o = out2 + (size_t)row * D_F2 + gl;
    o[0]  = make_float2(ax0, ay0);
    o[8]  = make_float2(ax1, ay1);
    o[16] = make_float2(ax2, ay2);
}

extern "C" void kernel_launch(void* const* d_in, const int* in_sizes, int n_in,
                              void* d_out, int out_size) {
    const int*   rows   = (const int*)d_in[0];
    const int*   cols   = (const int*)d_in[1];
    const float* vals   = (const float*)d_in[2];
    const float2* embeds2 = (const float2*)d_in[3];
    float2* out2 = (float2*)d_out;

    int n_edges = in_sizes[0];
    int n4 = n_edges / 4;   // 1.6M divisible by 4

    hist_kernel<<<(n4 + 255) / 256, 256>>>((const int4*)rows, n4);
    scan_lookback_kernel<<<SCAN_NB, SCAN_BLK>>>();
    scatter_kernel<<<(n4 + 255) / 256, 256>>>((const int4*)rows, (const int4*)cols,
                                              (const float4*)vals, n4);
    spmm_csr_kernel<<<N_NODES / 32, 256>>>(embeds2, out2);   // 3125 blocks
}